// round 2
// baseline (speedup 1.0000x reference)
#include <cuda_runtime.h>
#include <math.h>

#define Nn 10
#define Ee 64
#define Hh 128
#define Wd 256
#define Mm 16
#define HW 32768
#define NEHW 20971520
#define SCALE_O 0.005524271728019903f
#define PI_D 3.141592653589793238462643383279502884

// ---------------- static device scratch ----------------
__device__ float  g_bufA[NEHW];            // 83.9 MB
__device__ float  g_bufB[NEHW];            // 83.9 MB
__device__ float2 g_fw [Nn*Ee*Hh*Mm];      // W-DFT result / inverse z
__device__ float2 g_cf [Nn*512*Ee];        // fwd coeff   [n][mode][e]
__device__ float2 g_cf2[Nn*512*Ee];        // spectral out [n][mode][o]
__device__ float2 g_wt [8*256*64*64];      // transposed spectral weights (67 MB)
__device__ float4 g_wc [4*64*64];          // collapsed 2x2 phase conv weights
__device__ float  g_twfw[Wd*32];           // fwd W twiddles [w][2k]=cos,[2k+1]=-sin
__device__ float2 g_twh [Hh*32];           // H twiddles [h][r] = (cos,sin) of +2*pi*rf*h/128
__device__ float  g_tiw [32*Wd];           // inverse-W table [j][w] (scale folded in)
__device__ float2 g_pstat[Nn*Ee*32];       // per-strip partial (sum, sumsq)
__device__ float2 g_stats[Nn*Ee];          // (mean, inv_std)

__device__ __forceinline__ float gelu_f(float x) {
    return 0.5f * x * (1.0f + erff(x * 0.70710678118654752f));
}

// ---------------- prep kernels ----------------
__global__ void k_prep_tw() {
    int t = blockIdx.x * blockDim.x + threadIdx.x;
    if (t < Wd * Mm) {
        int w = t >> 4, k = t & 15;
        double ang = 2.0 * PI_D * (double)(k * w) / (double)Wd;
        double s, c; sincos(ang, &s, &c);
        g_twfw[w * 32 + 2 * k]     = (float)c;
        g_twfw[w * 32 + 2 * k + 1] = (float)(-s);
        float fk = (k == 0) ? 1.0f : 2.0f;
        g_tiw[(2 * k) * Wd + w]     = fk * (float)c * SCALE_O;
        g_tiw[(2 * k + 1) * Wd + w] = (k == 0) ? 0.0f : (-2.0f * (float)s * SCALE_O);
    } else if (t < 8192) {
        int t2 = t - 4096;
        int h = t2 >> 5, r = t2 & 31;
        int rf = (r < 16) ? r : r + 96;
        double ang = 2.0 * PI_D * (double)(rf * h) / (double)Hh;
        double s, c; sincos(ang, &s, &c);
        g_twh[h * 32 + r] = make_float2((float)c, (float)s);
    }
}

__device__ __forceinline__ bool in_set(int a, int s, int k) {
    return a == 0 ? (s == 0 ? (k == 0) : (k >= 1))
                  : (s == 0 ? (k <= 1) : (k == 2));
}

__global__ void k_prep_wc(const float* __restrict__ w3) {
    int t = blockIdx.x * blockDim.x + threadIdx.x;
    if (t >= 16384) return;
    int ph = t >> 12;
    int o  = (t >> 6) & 63;
    int i  = t & 63;
    int a = ph >> 1, b = ph & 1;
    const float* wk = w3 + (o * 64 + i) * 9;
    float v[4];
    #pragma unroll
    for (int s = 0; s < 2; s++)
        #pragma unroll
        for (int tt = 0; tt < 2; tt++) {
            float acc = 0.f;
            for (int ky = 0; ky < 3; ky++)
                if (in_set(a, s, ky))
                    for (int kx = 0; kx < 3; kx++)
                        if (in_set(b, tt, kx)) acc += wk[ky * 3 + kx];
            v[s * 2 + tt] = acc;
        }
    g_wc[t] = make_float4(v[0], v[1], v[2], v[3]);
}

__global__ void k_prep_wt(const float* __restrict__ wr, const float* __restrict__ wi) {
    int t = blockIdx.x * blockDim.x + threadIdx.x;   // 8388608 total
    int m  = t & 255;
    int o  = (t >> 8) & 63;
    int i  = (t >> 14) & 63;
    int lq = t >> 20;
    int src = (((lq * 64 + i) * 64 + o) << 8) + m;
    g_wt[((size_t)(lq * 256 + m) * 64 + i) * 64 + o] = make_float2(wr[src], wi[src]);
}

// ---------------- pipeline ----------------
__global__ void k_updim(const float* __restrict__ in, const float* __restrict__ uw,
                        const float* __restrict__ ub) {
    int idx = blockIdx.x * blockDim.x + threadIdx.x;
    if (idx >= NEHW) return;
    int p  = idx & (HW - 1);
    int ne = idx >> 15;
    int e = ne & 63, n = ne >> 6;
    float x0 = in[(size_t)(n * 2)     * HW + p];
    float x1 = in[(size_t)(n * 2 + 1) * HW + p];
    g_bufA[idx] = fmaf(uw[e * 2], x0, fmaf(uw[e * 2 + 1], x1, ub[e]));
}

// 4-phase collapsed conv3x3-on-upsampled + deterministic partial stats.
// grid (32 strips, 16 eo-groups, 10 n), 256 threads: tx=w-group(64x4 cols), ty=row(4)
__global__ __launch_bounds__(256) void k_conv_phases() {
    __shared__ float4 ws4[4][64][4];     // [eol][i][ph]
    __shared__ float  tile[6][260];
    __shared__ float2 red[256];
    int tid = threadIdx.x;
    int tx = tid & 63, ty = tid >> 6;
    int strip = blockIdx.x, eog = blockIdx.y, n = blockIdx.z;
    int h0 = strip * 4;
    int w0 = tx * 4;

    for (int idx = tid; idx < 1024; idx += 256) {
        int eol = idx >> 8, ii = (idx >> 2) & 63, ph = idx & 3;
        ws4[eol][ii][ph] = g_wc[ph * 4096 + (eog * 4 + eol) * 64 + ii];
    }
    if (tid < 6) { tile[tid][0] = 0.f; tile[tid][257] = 0.f; }

    float acc[4][4][4];
    #pragma unroll
    for (int a = 0; a < 4; a++)
        #pragma unroll
        for (int b = 0; b < 4; b++)
            #pragma unroll
            for (int c = 0; c < 4; c++) acc[a][b][c] = 0.f;

    const float* xb = g_bufA + (size_t)(n * 64) * HW;
    for (int i = 0; i < 64; i++) {
        __syncthreads();
        #pragma unroll
        for (int rr = 0; rr < 6; rr++) {
            int hg = h0 - 1 + rr;
            float v = 0.f;
            if (hg >= 0 && hg < Hh) v = xb[(size_t)i * HW + hg * Wd + tid];
            tile[rr][tid + 1] = v;
        }
        __syncthreads();
        float xr[3][6];
        #pragma unroll
        for (int r = 0; r < 3; r++)
            #pragma unroll
            for (int cc = 0; cc < 6; cc++) xr[r][cc] = tile[ty + r][w0 + cc];
        #pragma unroll
        for (int eol = 0; eol < 4; eol++) {
            float4 vv[4];
            #pragma unroll
            for (int ph = 0; ph < 4; ph++) vv[ph] = ws4[eol][i][ph];
            #pragma unroll
            for (int a = 0; a < 2; a++)
                #pragma unroll
                for (int b = 0; b < 2; b++) {
                    int ph = a * 2 + b;
                    #pragma unroll
                    for (int c = 0; c < 4; c++) {
                        float s = vv[ph].x * xr[a][c + b]
                                + vv[ph].y * xr[a][c + b + 1]
                                + vv[ph].z * xr[a + 1][c + b]
                                + vv[ph].w * xr[a + 1][c + b + 1];
                        acc[eol][ph][c] += s;
                    }
                }
        }
    }

    // phase (0,0) is the carried value (resize takes even pixels)
    #pragma unroll
    for (int eol = 0; eol < 4; eol++) {
        int eo = eog * 4 + eol;
        float4 st = make_float4(acc[eol][0][0], acc[eol][0][1], acc[eol][0][2], acc[eol][0][3]);
        *(float4*)&g_bufB[((size_t)(n * 64 + eo) * Hh + h0 + ty) * Wd + w0] = st;
    }
    // deterministic per-block partial stats over all 4 phases
    for (int eol = 0; eol < 4; eol++) {
        float s = 0.f, q = 0.f;
        #pragma unroll
        for (int ph = 0; ph < 4; ph++)
            #pragma unroll
            for (int c = 0; c < 4; c++) {
                float v = acc[eol][ph][c];
                s += v; q += v * v;
            }
        __syncthreads();
        red[tid] = make_float2(s, q);
        __syncthreads();
        for (int off = 128; off > 0; off >>= 1) {
            if (tid < off) {
                red[tid].x += red[tid + off].x;
                red[tid].y += red[tid + off].y;
            }
            __syncthreads();
        }
        if (tid == 0)
            g_pstat[(n * 64 + eog * 4 + eol) * 32 + strip] = red[0];
    }
}

__global__ void k_stats() {
    int b = blockIdx.x;
    int t = threadIdx.x;  // 32
    float2 v = g_pstat[b * 32 + t];
    float s = v.x, q = v.y;
    #pragma unroll
    for (int off = 16; off > 0; off >>= 1) {
        s += __shfl_down_sync(0xffffffffu, s, off);
        q += __shfl_down_sync(0xffffffffu, q, off);
    }
    if (t == 0) {
        float mean = s * (1.0f / 131072.0f);
        float var  = q * (1.0f / 131072.0f) - mean * mean;
        g_stats[b] = make_float2(mean, rsqrtf(var + 1e-5f));
    }
}

__global__ void k_norm_gelu() {
    int idx = blockIdx.x * blockDim.x + threadIdx.x;
    if (idx >= NEHW) return;
    float2 st = g_stats[idx >> 15];
    float v = (g_bufB[idx] - st.x) * st.y;
    g_bufA[idx] = gelu_f(v);
}

__global__ __launch_bounds__(256) void k_conv1x1(const float* __restrict__ cw,
                                                 const float* __restrict__ cb) {
    __shared__ float sw[4096];
    __shared__ float sb[64];
    int tid = threadIdx.x;
    int n = blockIdx.y;
    int p = blockIdx.x * 256 + tid;
    for (int idx = tid; idx < 4096; idx += 256) sw[idx] = cw[idx];
    if (tid < 64) sb[tid] = cb[tid];
    __syncthreads();
    float xv[64];
    const float* xb = g_bufA + (size_t)n * 64 * HW + p;
    #pragma unroll
    for (int i = 0; i < 64; i++) xv[i] = xb[(size_t)i * HW];
    float* ob = g_bufB + (size_t)n * 64 * HW + p;
    for (int o = 0; o < 64; o++) {
        float a = sb[o];
        const float4* w4 = (const float4*)(sw + o * 64);
        #pragma unroll
        for (int i4 = 0; i4 < 16; i4++) {
            float4 w = w4[i4];
            a = fmaf(w.x, xv[4 * i4],     a);
            a = fmaf(w.y, xv[4 * i4 + 1], a);
            a = fmaf(w.z, xv[4 * i4 + 2], a);
            a = fmaf(w.w, xv[4 * i4 + 3], a);
        }
        ob[(size_t)o * HW] = a;
    }
}

// forward W-DFT: Zw[row][k] = sum_w x[row][w] * e^{-2pi i k w / 256}
__global__ __launch_bounds__(256) void k_fwdW() {
    __shared__ float smx[32 * 256];
    int tid = threadIdx.x;
    int row0 = blockIdx.x * 32;
    for (int idx = tid; idx < 8192; idx += 256)
        smx[idx] = g_bufA[(size_t)row0 * 256 + idx];
    __syncthreads();
    int k = tid & 15, rg = tid >> 4;
    int r0 = rg * 2, r1 = rg * 2 + 1;
    float a0r = 0, a0i = 0, a1r = 0, a1i = 0;
    const float2* twp = (const float2*)g_twfw;   // [w*16 + k]
    #pragma unroll 4
    for (int w = 0; w < 256; w++) {
        float2 tw = twp[w * 16 + k];
        float x0 = smx[r0 * 256 + w], x1 = smx[r1 * 256 + w];
        a0r = fmaf(x0, tw.x, a0r); a0i = fmaf(x0, tw.y, a0i);
        a1r = fmaf(x1, tw.x, a1r); a1i = fmaf(x1, tw.y, a1i);
    }
    g_fw[(size_t)(row0 + r0) * 16 + k] = make_float2(a0r, a0i);
    g_fw[(size_t)(row0 + r1) * 16 + k] = make_float2(a1r, a1i);
}

// forward H-DFT (rows 0..15 & 112..127), applies ortho scale
__global__ __launch_bounds__(256) void k_fwdH() {
    __shared__ float2 smz[2048];
    int tid = threadIdx.x;
    int b = blockIdx.x;          // n*64 + e
    int n = b >> 6, e = b & 63;
    for (int idx = tid; idx < 2048; idx += 256)
        smz[idx] = g_fw[(size_t)b * 2048 + idx];
    __syncthreads();
    for (int o = tid; o < 512; o += 256) {
        int r = o >> 4, k = o & 15;
        float ar = 0, ai = 0;
        #pragma unroll 4
        for (int h = 0; h < 128; h++) {
            float2 z = smz[h * 16 + k];
            float2 t = g_twh[h * 32 + r];   // e^{-i}: (c, -s)
            ar += z.x * t.x + z.y * t.y;
            ai += z.y * t.x - z.x * t.y;
        }
        g_cf[((size_t)n * 512 + o) * 64 + e] = make_float2(ar * SCALE_O, ai * SCALE_O);
    }
}

// spectral multiply: out[o] = sum_i c[i] * W[i,o]  (complex)
__global__ __launch_bounds__(128) void k_spec(int l) {
    __shared__ float2 sc[128];
    int tid = threadIdx.x;
    int n = blockIdx.y;
    int mload = blockIdx.x * 2 + (tid >> 6);
    sc[tid] = g_cf[((size_t)n * 512 + mload) * 64 + (tid & 63)];
    __syncthreads();
    int half = tid >> 6, o = tid & 63;
    int m = blockIdx.x * 2 + half;
    int r = m >> 4, k = m & 15;
    int q = r >> 4;
    int m2 = (r & 15) * 16 + k;
    const float2* wp = g_wt + (size_t)((l * 2 + q) * 256 + m2) * 4096 + o;
    const float2* cp = sc + (half << 6);
    float ar = 0, ai = 0;
    #pragma unroll 4
    for (int i = 0; i < 64; i++) {
        float2 c = cp[i];
        float2 w = wp[(size_t)i * 64];
        ar += c.x * w.x - c.y * w.y;
        ai += c.x * w.y + c.y * w.x;
    }
    g_cf2[((size_t)n * 512 + m) * 64 + o] = make_float2(ar, ai);
}

// inverse H (full complex ifft, only 32 nonzero rows)
__global__ __launch_bounds__(256) void k_invH() {
    __shared__ float2 sz[512];
    int tid = threadIdx.x;
    int b = blockIdx.x;   // n*64 + o
    int n = b >> 6, oo = b & 63;
    for (int m = tid; m < 512; m += 256)
        sz[m] = g_cf2[((size_t)n * 512 + m) * 64 + oo];
    __syncthreads();
    for (int oi = tid; oi < 2048; oi += 256) {
        int h = oi >> 4, k = oi & 15;
        float ar = 0, ai = 0;
        #pragma unroll
        for (int r = 0; r < 32; r++) {
            float2 sp = sz[r * 16 + k];
            float2 t = g_twh[h * 32 + r];   // e^{+i}: (c, s)
            ar += sp.x * t.x - sp.y * t.y;
            ai += sp.x * t.y + sp.y * t.x;
        }
        g_fw[(size_t)b * 2048 + oi] = make_float2(ar, ai);
    }
}

// inverse W (C2R, Im z0 discarded via table) + conv1x1 add + gelu
__global__ __launch_bounds__(256) void k_invW_gelu() {
    __shared__ float szs[8][32];
    int tid = threadIdx.x;
    int row0 = blockIdx.x * 8;
    if (tid < 128)
        ((float2*)szs)[tid] = g_fw[(size_t)row0 * 16 + tid];
    __syncthreads();
    int tx = tid & 63, ry = tid >> 6;
    int w0 = tx * 4;
    int rA = ry * 2, rB = ry * 2 + 1;
    float aA0 = 0, aA1 = 0, aA2 = 0, aA3 = 0;
    float aB0 = 0, aB1 = 0, aB2 = 0, aB3 = 0;
    const float4* tp = (const float4*)g_tiw;   // [j*64 + tx]
    #pragma unroll 4
    for (int j = 0; j < 32; j++) {
        float4 tv = tp[j * 64 + tx];
        float zA = szs[rA][j], zB = szs[rB][j];
        aA0 = fmaf(zA, tv.x, aA0); aA1 = fmaf(zA, tv.y, aA1);
        aA2 = fmaf(zA, tv.z, aA2); aA3 = fmaf(zA, tv.w, aA3);
        aB0 = fmaf(zB, tv.x, aB0); aB1 = fmaf(zB, tv.y, aB1);
        aB2 = fmaf(zB, tv.z, aB2); aB3 = fmaf(zB, tv.w, aB3);
    }
    size_t base = (size_t)row0 * 256;
    float4 cA = *(const float4*)&g_bufB[base + (size_t)rA * 256 + w0];
    float4 cB = *(const float4*)&g_bufB[base + (size_t)rB * 256 + w0];
    float4 oA = make_float4(gelu_f(aA0 + cA.x), gelu_f(aA1 + cA.y),
                            gelu_f(aA2 + cA.z), gelu_f(aA3 + cA.w));
    float4 oB = make_float4(gelu_f(aB0 + cB.x), gelu_f(aB1 + cB.y),
                            gelu_f(aB2 + cB.z), gelu_f(aB3 + cB.w));
    *(float4*)&g_bufA[base + (size_t)rA * 256 + w0] = oA;
    *(float4*)&g_bufA[base + (size_t)rB * 256 + w0] = oB;
}

__global__ void k_downdim(const float* __restrict__ dw, const float* __restrict__ db,
                          float* __restrict__ out) {
    int t = blockIdx.x * blockDim.x + threadIdx.x;
    if (t >= Nn * HW) return;
    int n = t >> 15, p = t & (HW - 1);
    float c0 = db[0], c1 = db[1];
    const float* xb = g_bufA + (size_t)n * 64 * HW + p;
    #pragma unroll 4
    for (int e = 0; e < 64; e++) {
        float v = xb[(size_t)e * HW];
        c0 = fmaf(dw[e], v, c0);
        c1 = fmaf(dw[64 + e], v, c1);
    }
    out[(size_t)(n * 2) * HW + p]     = c0;
    out[(size_t)(n * 2 + 1) * HW + p] = c1;
}

extern "C" void kernel_launch(void* const* d_in, const int* in_sizes, int n_in,
                              void* d_out, int out_size) {
    (void)in_sizes; (void)n_in; (void)out_size;
    const float* sensor    = (const float*)d_in[0];
    const float* updim_w   = (const float*)d_in[1];
    const float* updim_b   = (const float*)d_in[2];
    const float* smooth_w  = (const float*)d_in[3];
    // d_in[4] smooth_b: cancels exactly under InstanceNorm(affine=False)
    const float* fno_wr    = (const float*)d_in[5];
    const float* fno_wi    = (const float*)d_in[6];
    const float* fno_cw    = (const float*)d_in[7];
    const float* fno_cb    = (const float*)d_in[8];
    const float* downdim_w = (const float*)d_in[9];
    const float* downdim_b = (const float*)d_in[10];
    float* out = (float*)d_out;

    k_prep_tw<<<32, 256>>>();
    k_prep_wc<<<64, 256>>>(smooth_w);
    k_prep_wt<<<32768, 256>>>(fno_wr, fno_wi);

    k_updim<<<NEHW / 256, 256>>>(sensor, updim_w, updim_b);
    k_conv_phases<<<dim3(32, 16, 10), 256>>>();
    k_stats<<<640, 32>>>();
    k_norm_gelu<<<NEHW / 256, 256>>>();

    for (int l = 0; l < 4; l++) {
        k_conv1x1<<<dim3(128, 10), 256>>>(fno_cw + l * 4096, fno_cb + l * 64);
        k_fwdW<<<2560, 256>>>();
        k_fwdH<<<640, 256>>>();
        k_spec<<<dim3(256, 10), 128>>>(l);
        k_invH<<<640, 256>>>();
        k_invW_gelu<<<10240, 256>>>();
    }

    k_downdim<<<(Nn * HW + 255) / 256, 256>>>(downdim_w, downdim_b, out);
}

// round 3
// speedup vs baseline: 1.1154x; 1.1154x over previous
#include <cuda_runtime.h>
#include <math.h>

#define Nn 10
#define Ee 64
#define Hh 128
#define Wd 256
#define Mm 16
#define HW 32768
#define NEHW 20971520
#define SCALE_O 0.005524271728019903f
#define PI_D 3.141592653589793238462643383279502884

// ---------------- static device scratch ----------------
__device__ float  g_bufA[NEHW];            // 83.9 MB
__device__ float  g_bufB[NEHW];            // 83.9 MB
__device__ float2 g_fw [Nn*Ee*Hh*Mm];      // W-DFT result / inverse z
__device__ float2 g_cf [Nn*512*Ee];        // fwd coeff   [n][mode][e]
__device__ float2 g_cf2[Nn*512*Ee];        // spectral out [n][mode][o]
__device__ float2 g_wt [8*256*64*64];      // transposed spectral weights (67 MB)
__device__ float4 g_wc [4*64*64];          // collapsed 2x2 phase conv weights
__device__ float  g_twfw[Wd*32];           // fwd W twiddles [w][2k]=cos,[2k+1]=-sin
__device__ float2 g_twh [Hh*32];           // H twiddles [h][r]
__device__ float  g_tiw [32*Wd];           // inverse-W table [j][w] (scale folded)
__device__ float2 g_pstat[Nn*Ee*32];       // per-strip partial (sum, sumsq)
__device__ float2 g_stats[Nn*Ee];          // (mean, inv_std)

__device__ __forceinline__ float gelu_f(float x) {
    return 0.5f * x * (1.0f + erff(x * 0.70710678118654752f));
}

// ---------------- prep kernels ----------------
__global__ void k_prep_tw() {
    int t = blockIdx.x * blockDim.x + threadIdx.x;
    if (t < Wd * Mm) {
        int w = t >> 4, k = t & 15;
        double ang = 2.0 * PI_D * (double)(k * w) / (double)Wd;
        double s, c; sincos(ang, &s, &c);
        g_twfw[w * 32 + 2 * k]     = (float)c;
        g_twfw[w * 32 + 2 * k + 1] = (float)(-s);
        float fk = (k == 0) ? 1.0f : 2.0f;
        g_tiw[(2 * k) * Wd + w]     = fk * (float)c * SCALE_O;
        g_tiw[(2 * k + 1) * Wd + w] = (k == 0) ? 0.0f : (-2.0f * (float)s * SCALE_O);
    } else if (t < 8192) {
        int t2 = t - 4096;
        int h = t2 >> 5, r = t2 & 31;
        int rf = (r < 16) ? r : r + 96;
        double ang = 2.0 * PI_D * (double)(rf * h) / (double)Hh;
        double s, c; sincos(ang, &s, &c);
        g_twh[h * 32 + r] = make_float2((float)c, (float)s);
    }
}

__device__ __forceinline__ bool in_set(int a, int s, int k) {
    return a == 0 ? (s == 0 ? (k == 0) : (k >= 1))
                  : (s == 0 ? (k <= 1) : (k == 2));
}

__global__ void k_prep_wc(const float* __restrict__ w3) {
    int t = blockIdx.x * blockDim.x + threadIdx.x;
    if (t >= 16384) return;
    int ph = t >> 12;
    int o  = (t >> 6) & 63;
    int i  = t & 63;
    int a = ph >> 1, b = ph & 1;
    const float* wk = w3 + (o * 64 + i) * 9;
    float v[4];
    #pragma unroll
    for (int s = 0; s < 2; s++)
        #pragma unroll
        for (int tt = 0; tt < 2; tt++) {
            float acc = 0.f;
            for (int ky = 0; ky < 3; ky++)
                if (in_set(a, s, ky))
                    for (int kx = 0; kx < 3; kx++)
                        if (in_set(b, tt, kx)) acc += wk[ky * 3 + kx];
            v[s * 2 + tt] = acc;
        }
    g_wc[t] = make_float4(v[0], v[1], v[2], v[3]);
}

__global__ void k_prep_wt(const float* __restrict__ wr, const float* __restrict__ wi) {
    int t = blockIdx.x * blockDim.x + threadIdx.x;   // 8388608 total
    int m  = t & 255;
    int o  = (t >> 8) & 63;
    int i  = (t >> 14) & 63;
    int lq = t >> 20;
    int src = (((lq * 64 + i) * 64 + o) << 8) + m;
    g_wt[((size_t)(lq * 256 + m) * 64 + i) * 64 + o] = make_float2(wr[src], wi[src]);
}

// ---------------- pipeline ----------------
__global__ void k_updim(const float* __restrict__ in, const float* __restrict__ uw,
                        const float* __restrict__ ub) {
    int idx = blockIdx.x * blockDim.x + threadIdx.x;   // NEHW/4 threads
    if (idx >= NEHW / 4) return;
    int p4 = (idx & 8191) << 2;
    int ne = idx >> 13;
    int e = ne & 63, n = ne >> 6;
    float4 x0 = *(const float4*)&in[(size_t)(n * 2)     * HW + p4];
    float4 x1 = *(const float4*)&in[(size_t)(n * 2 + 1) * HW + p4];
    float w0 = uw[e * 2], w1 = uw[e * 2 + 1], b = ub[e];
    float4 r;
    r.x = fmaf(w0, x0.x, fmaf(w1, x1.x, b));
    r.y = fmaf(w0, x0.y, fmaf(w1, x1.y, b));
    r.z = fmaf(w0, x0.z, fmaf(w1, x1.z, b));
    r.w = fmaf(w0, x0.w, fmaf(w1, x1.w, b));
    *(float4*)&g_bufA[(size_t)ne * HW + p4] = r;
}

// 4-phase collapsed conv3x3-on-upsampled + deterministic partial stats.
// grid (32 strips, 8 eo-groups of 8, 10 n), 256 threads: tx=w(64x4 cols), ty=row(4)
__global__ __launch_bounds__(256, 1) void k_conv_phases() {
    __shared__ float4 ws4[8][64][4];     // [eol][i][ph]  32 KB
    __shared__ float  tile[2][6][260];   // 12.5 KB
    __shared__ float2 red2[8][8];
    int tid = threadIdx.x;
    int tx = tid & 63, ty = tid >> 6;
    int strip = blockIdx.x, eog = blockIdx.y, n = blockIdx.z;
    int h0 = strip * 4;
    int w0 = tx * 4;

    for (int idx = tid; idx < 2048; idx += 256) {
        int eol = idx >> 8, ii = (idx >> 2) & 63, ph = idx & 3;
        ws4[eol][ii][ph] = g_wc[ph * 4096 + (eog * 8 + eol) * 64 + ii];
    }
    if (tid < 6) {
        tile[0][tid][0] = 0.f; tile[0][tid][257] = 0.f;
        tile[1][tid][0] = 0.f; tile[1][tid][257] = 0.f;
    }

    float acc[8][16];
    #pragma unroll
    for (int a = 0; a < 8; a++)
        #pragma unroll
        for (int b = 0; b < 16; b++) acc[a][b] = 0.f;

    const float* xb = g_bufA + (size_t)(n * 64) * HW;
    for (int i = 0; i < 64; i += 2) {
        __syncthreads();
        #pragma unroll
        for (int rr = 0; rr < 6; rr++) {
            int hg = h0 - 1 + rr;
            float v0 = 0.f, v1 = 0.f;
            if (hg >= 0 && hg < Hh) {
                const float* rowp = xb + (size_t)i * HW + hg * Wd + tid;
                v0 = rowp[0];
                v1 = rowp[HW];
            }
            tile[0][rr][tid + 1] = v0;
            tile[1][rr][tid + 1] = v1;
        }
        __syncthreads();
        #pragma unroll
        for (int t2 = 0; t2 < 2; t2++) {
            int ch = i + t2;
            float xr[3][6];
            #pragma unroll
            for (int r = 0; r < 3; r++)
                #pragma unroll
                for (int cc = 0; cc < 6; cc++) xr[r][cc] = tile[t2][ty + r][w0 + cc];
            #pragma unroll
            for (int eol = 0; eol < 8; eol++) {
                float4 v00 = ws4[eol][ch][0];
                float4 v01 = ws4[eol][ch][1];
                float4 v10 = ws4[eol][ch][2];
                float4 v11 = ws4[eol][ch][3];
                float* ac = acc[eol];
                #pragma unroll
                for (int c = 0; c < 4; c++) {
                    ac[c]      = fmaf(v00.x, xr[0][c],
                                 fmaf(v00.y, xr[0][c + 1],
                                 fmaf(v00.z, xr[1][c],
                                 fmaf(v00.w, xr[1][c + 1], ac[c]))));
                    ac[4 + c]  = fmaf(v01.x, xr[0][c + 1],
                                 fmaf(v01.y, xr[0][c + 2],
                                 fmaf(v01.z, xr[1][c + 1],
                                 fmaf(v01.w, xr[1][c + 2], ac[4 + c]))));
                    ac[8 + c]  = fmaf(v10.x, xr[1][c],
                                 fmaf(v10.y, xr[1][c + 1],
                                 fmaf(v10.z, xr[2][c],
                                 fmaf(v10.w, xr[2][c + 1], ac[8 + c]))));
                    ac[12 + c] = fmaf(v11.x, xr[1][c + 1],
                                 fmaf(v11.y, xr[1][c + 2],
                                 fmaf(v11.z, xr[2][c + 1],
                                 fmaf(v11.w, xr[2][c + 2], ac[12 + c]))));
                }
            }
        }
    }

    // phase (0,0) is the carried value (resize takes even pixels)
    #pragma unroll
    for (int eol = 0; eol < 8; eol++) {
        int eo = eog * 8 + eol;
        float4 st = make_float4(acc[eol][0], acc[eol][1], acc[eol][2], acc[eol][3]);
        *(float4*)&g_bufB[((size_t)(n * 64 + eo) * Hh + h0 + ty) * Wd + w0] = st;
    }
    // deterministic partial stats over all 4 phases (warp shuffle + smem)
    int lane = tid & 31, wid = tid >> 5;
    #pragma unroll
    for (int eol = 0; eol < 8; eol++) {
        float s = 0.f, q = 0.f;
        #pragma unroll
        for (int j = 0; j < 16; j++) {
            float v = acc[eol][j];
            s += v; q += v * v;
        }
        #pragma unroll
        for (int off = 16; off > 0; off >>= 1) {
            s += __shfl_down_sync(0xffffffffu, s, off);
            q += __shfl_down_sync(0xffffffffu, q, off);
        }
        if (lane == 0) red2[eol][wid] = make_float2(s, q);
    }
    __syncthreads();
    if (tid < 8) {
        float s = 0.f, q = 0.f;
        #pragma unroll
        for (int w = 0; w < 8; w++) {
            float2 v = red2[tid][w];
            s += v.x; q += v.y;
        }
        g_pstat[(n * 64 + eog * 8 + tid) * 32 + strip] = make_float2(s, q);
    }
}

__global__ void k_stats() {
    int b = blockIdx.x;
    int t = threadIdx.x;  // 32
    float2 v = g_pstat[b * 32 + t];
    float s = v.x, q = v.y;
    #pragma unroll
    for (int off = 16; off > 0; off >>= 1) {
        s += __shfl_down_sync(0xffffffffu, s, off);
        q += __shfl_down_sync(0xffffffffu, q, off);
    }
    if (t == 0) {
        float mean = s * (1.0f / 131072.0f);
        float var  = q * (1.0f / 131072.0f) - mean * mean;
        g_stats[b] = make_float2(mean, rsqrtf(var + 1e-5f));
    }
}

// conv1x1; when first!=0 the input is g_bufB (raw conv output): apply
// InstanceNorm+gelu on load and write the normalized x back to g_bufA
// (needed by the FFT path). In-place g_bufB overwrite is safe: each (ch,p)
// element is read/written by exactly one thread, reads precede writes.
__global__ __launch_bounds__(256) void k_conv1x1(const float* __restrict__ cw,
                                                 const float* __restrict__ cb,
                                                 int first) {
    __shared__ float sw[4096];
    __shared__ float sb[64];
    __shared__ float2 sst[64];
    int tid = threadIdx.x;
    int n = blockIdx.y;
    int p = blockIdx.x * 256 + tid;
    for (int idx = tid; idx < 4096; idx += 256) sw[idx] = cw[idx];
    if (tid < 64) {
        sb[tid] = cb[tid];
        if (first) sst[tid] = g_stats[n * 64 + tid];
    }
    __syncthreads();
    float xv[64];
    const float* xb = (first ? g_bufB : g_bufA) + (size_t)n * 64 * HW + p;
    float* xout = g_bufA + (size_t)n * 64 * HW + p;
    #pragma unroll
    for (int i = 0; i < 64; i++) {
        float v = xb[(size_t)i * HW];
        if (first) {
            float2 st = sst[i];
            v = gelu_f((v - st.x) * st.y);
            xout[(size_t)i * HW] = v;
        }
        xv[i] = v;
    }
    float* ob = g_bufB + (size_t)n * 64 * HW + p;
    for (int o = 0; o < 64; o++) {
        float a = sb[o];
        const float4* w4 = (const float4*)(sw + o * 64);
        #pragma unroll
        for (int i4 = 0; i4 < 16; i4++) {
            float4 w = w4[i4];
            a = fmaf(w.x, xv[4 * i4],     a);
            a = fmaf(w.y, xv[4 * i4 + 1], a);
            a = fmaf(w.z, xv[4 * i4 + 2], a);
            a = fmaf(w.w, xv[4 * i4 + 3], a);
        }
        ob[(size_t)o * HW] = a;
    }
}

// forward W-DFT: Zw[row][k] = sum_w x[row][w] * e^{-2pi i k w / 256}
__global__ __launch_bounds__(256) void k_fwdW() {
    __shared__ float smx[32 * 256];
    int tid = threadIdx.x;
    int row0 = blockIdx.x * 32;
    for (int idx = tid; idx < 8192; idx += 256)
        smx[idx] = g_bufA[(size_t)row0 * 256 + idx];
    __syncthreads();
    int k = tid & 15, rg = tid >> 4;
    int r0 = rg * 2, r1 = rg * 2 + 1;
    float a0r = 0, a0i = 0, a1r = 0, a1i = 0;
    const float2* twp = (const float2*)g_twfw;   // [w*16 + k]
    #pragma unroll 4
    for (int w = 0; w < 256; w++) {
        float2 tw = twp[w * 16 + k];
        float x0 = smx[r0 * 256 + w], x1 = smx[r1 * 256 + w];
        a0r = fmaf(x0, tw.x, a0r); a0i = fmaf(x0, tw.y, a0i);
        a1r = fmaf(x1, tw.x, a1r); a1i = fmaf(x1, tw.y, a1i);
    }
    g_fw[(size_t)(row0 + r0) * 16 + k] = make_float2(a0r, a0i);
    g_fw[(size_t)(row0 + r1) * 16 + k] = make_float2(a1r, a1i);
}

// forward H-DFT (rows 0..15 & 112..127), applies ortho scale
__global__ __launch_bounds__(256) void k_fwdH() {
    __shared__ float2 smz[2048];
    int tid = threadIdx.x;
    int b = blockIdx.x;          // n*64 + e
    int n = b >> 6, e = b & 63;
    for (int idx = tid; idx < 2048; idx += 256)
        smz[idx] = g_fw[(size_t)b * 2048 + idx];
    __syncthreads();
    for (int o = tid; o < 512; o += 256) {
        int r = o >> 4, k = o & 15;
        float ar = 0, ai = 0;
        #pragma unroll 4
        for (int h = 0; h < 128; h++) {
            float2 z = smz[h * 16 + k];
            float2 t = g_twh[h * 32 + r];   // e^{-i}: (c, -s)
            ar += z.x * t.x + z.y * t.y;
            ai += z.y * t.x - z.x * t.y;
        }
        g_cf[((size_t)n * 512 + o) * 64 + e] = make_float2(ar * SCALE_O, ai * SCALE_O);
    }
}

// spectral multiply: one block per mode m, all 10 batch images per block
// (weights read once), out[o] = sum_i c[i] * W[i,o]  (complex)
__global__ __launch_bounds__(128) void k_spec(int l) {
    __shared__ float2 sc[10][64];
    int tid = threadIdx.x;
    int m = blockIdx.x;            // 0..511
    for (int idx = tid; idx < 640; idx += 128) {
        int n = idx >> 6, i = idx & 63;
        sc[n][i] = g_cf[((size_t)n * 512 + m) * 64 + i];
    }
    __syncthreads();
    int o = tid & 63, nh = tid >> 6;    // nh in {0,1}: n = nh*5 + j
    int r = m >> 4, k = m & 15;
    int q = r >> 4;
    int m2 = (r & 15) * 16 + k;
    const float2* wp = g_wt + (size_t)((l * 2 + q) * 256 + m2) * 4096 + o;
    float ar[5] = {0, 0, 0, 0, 0}, ai[5] = {0, 0, 0, 0, 0};
    #pragma unroll 2
    for (int i = 0; i < 64; i++) {
        float2 w = wp[(size_t)i * 64];
        #pragma unroll
        for (int j = 0; j < 5; j++) {
            float2 c = sc[nh * 5 + j][i];
            ar[j] = fmaf(c.x, w.x, fmaf(-c.y, w.y, ar[j]));
            ai[j] = fmaf(c.x, w.y, fmaf(c.y, w.x, ai[j]));
        }
    }
    #pragma unroll
    for (int j = 0; j < 5; j++)
        g_cf2[((size_t)(nh * 5 + j) * 512 + m) * 64 + o] = make_float2(ar[j], ai[j]);
}

// inverse H (full complex ifft, only 32 nonzero rows)
__global__ __launch_bounds__(256) void k_invH() {
    __shared__ float2 sz[512];
    int tid = threadIdx.x;
    int b = blockIdx.x;   // n*64 + o
    int n = b >> 6, oo = b & 63;
    for (int m = tid; m < 512; m += 256)
        sz[m] = g_cf2[((size_t)n * 512 + m) * 64 + oo];
    __syncthreads();
    for (int oi = tid; oi < 2048; oi += 256) {
        int h = oi >> 4, k = oi & 15;
        float ar = 0, ai = 0;
        #pragma unroll
        for (int r = 0; r < 32; r++) {
            float2 sp = sz[r * 16 + k];
            float2 t = g_twh[h * 32 + r];   // e^{+i}: (c, s)
            ar += sp.x * t.x - sp.y * t.y;
            ai += sp.x * t.y + sp.y * t.x;
        }
        g_fw[(size_t)b * 2048 + oi] = make_float2(ar, ai);
    }
}

// inverse W (C2R, Im z0 discarded via table) + conv1x1 add + gelu
__global__ __launch_bounds__(256) void k_invW_gelu() {
    __shared__ float szs[8][32];
    int tid = threadIdx.x;
    int row0 = blockIdx.x * 8;
    if (tid < 128)
        ((float2*)szs)[tid] = g_fw[(size_t)row0 * 16 + tid];
    __syncthreads();
    int tx = tid & 63, ry = tid >> 6;
    int w0 = tx * 4;
    int rA = ry * 2, rB = ry * 2 + 1;
    float aA0 = 0, aA1 = 0, aA2 = 0, aA3 = 0;
    float aB0 = 0, aB1 = 0, aB2 = 0, aB3 = 0;
    const float4* tp = (const float4*)g_tiw;   // [j*64 + tx]
    #pragma unroll 4
    for (int j = 0; j < 32; j++) {
        float4 tv = tp[j * 64 + tx];
        float zA = szs[rA][j], zB = szs[rB][j];
        aA0 = fmaf(zA, tv.x, aA0); aA1 = fmaf(zA, tv.y, aA1);
        aA2 = fmaf(zA, tv.z, aA2); aA3 = fmaf(zA, tv.w, aA3);
        aB0 = fmaf(zB, tv.x, aB0); aB1 = fmaf(zB, tv.y, aB1);
        aB2 = fmaf(zB, tv.z, aB2); aB3 = fmaf(zB, tv.w, aB3);
    }
    size_t base = (size_t)row0 * 256;
    float4 cA = *(const float4*)&g_bufB[base + (size_t)rA * 256 + w0];
    float4 cB = *(const float4*)&g_bufB[base + (size_t)rB * 256 + w0];
    float4 oA = make_float4(gelu_f(aA0 + cA.x), gelu_f(aA1 + cA.y),
                            gelu_f(aA2 + cA.z), gelu_f(aA3 + cA.w));
    float4 oB = make_float4(gelu_f(aB0 + cB.x), gelu_f(aB1 + cB.y),
                            gelu_f(aB2 + cB.z), gelu_f(aB3 + cB.w));
    *(float4*)&g_bufA[base + (size_t)rA * 256 + w0] = oA;
    *(float4*)&g_bufA[base + (size_t)rB * 256 + w0] = oB;
}

__global__ __launch_bounds__(256) void k_downdim(const float* __restrict__ dw,
                                                 const float* __restrict__ db,
                                                 float* __restrict__ out) {
    __shared__ float sdw[128];
    __shared__ float sdb[2];
    int tid = threadIdx.x;
    if (tid < 128) sdw[tid] = dw[tid];
    if (tid < 2) sdb[tid] = db[tid];
    __syncthreads();
    int t = blockIdx.x * blockDim.x + tid;   // Nn*HW/4 threads
    if (t >= Nn * HW / 4) return;
    int n = t >> 13, p4 = (t & 8191) << 2;
    float4 c0 = make_float4(sdb[0], sdb[0], sdb[0], sdb[0]);
    float4 c1 = make_float4(sdb[1], sdb[1], sdb[1], sdb[1]);
    const float* xb = g_bufA + (size_t)n * 64 * HW + p4;
    #pragma unroll 4
    for (int e = 0; e < 64; e++) {
        float4 v = *(const float4*)&xb[(size_t)e * HW];
        float w0 = sdw[e], w1 = sdw[64 + e];
        c0.x = fmaf(w0, v.x, c0.x); c0.y = fmaf(w0, v.y, c0.y);
        c0.z = fmaf(w0, v.z, c0.z); c0.w = fmaf(w0, v.w, c0.w);
        c1.x = fmaf(w1, v.x, c1.x); c1.y = fmaf(w1, v.y, c1.y);
        c1.z = fmaf(w1, v.z, c1.z); c1.w = fmaf(w1, v.w, c1.w);
    }
    *(float4*)&out[(size_t)(n * 2) * HW + p4]     = c0;
    *(float4*)&out[(size_t)(n * 2 + 1) * HW + p4] = c1;
}

extern "C" void kernel_launch(void* const* d_in, const int* in_sizes, int n_in,
                              void* d_out, int out_size) {
    (void)in_sizes; (void)n_in; (void)out_size;
    const float* sensor    = (const float*)d_in[0];
    const float* updim_w   = (const float*)d_in[1];
    const float* updim_b   = (const float*)d_in[2];
    const float* smooth_w  = (const float*)d_in[3];
    // d_in[4] smooth_b: cancels exactly under InstanceNorm(affine=False)
    const float* fno_wr    = (const float*)d_in[5];
    const float* fno_wi    = (const float*)d_in[6];
    const float* fno_cw    = (const float*)d_in[7];
    const float* fno_cb    = (const float*)d_in[8];
    const float* downdim_w = (const float*)d_in[9];
    const float* downdim_b = (const float*)d_in[10];
    float* out = (float*)d_out;

    k_prep_tw<<<32, 256>>>();
    k_prep_wc<<<64, 256>>>(smooth_w);
    k_prep_wt<<<32768, 256>>>(fno_wr, fno_wi);

    k_updim<<<NEHW / 4 / 256, 256>>>(sensor, updim_w, updim_b);
    k_conv_phases<<<dim3(32, 8, 10), 256>>>();
    k_stats<<<640, 32>>>();

    for (int l = 0; l < 4; l++) {
        k_conv1x1<<<dim3(128, 10), 256>>>(fno_cw + l * 4096, fno_cb + l * 64,
                                          l == 0 ? 1 : 0);
        k_fwdW<<<2560, 256>>>();
        k_fwdH<<<640, 256>>>();
        k_spec<<<512, 128>>>(l);
        k_invH<<<640, 256>>>();
        k_invW_gelu<<<10240, 256>>>();
    }

    k_downdim<<<(Nn * HW / 4 + 255) / 256, 256>>>(downdim_w, downdim_b, out);
}